// round 16
// baseline (speedup 1.0000x reference)
#include <cuda_runtime.h>
#include <cuda_bf16.h>
#include <cstdint>

#define B_   64
#define A_   1024
#define D_   5
#define F_   256
#define NB_  6
#define O_   256
#define K_   262
#define KPAD 288
#define TM   64
#define NTHR 256
#define CHK  32
#define NC   9            // 9 uniform chunks of 32 k (k >= 262 zero-padded)
#define ROWS_TOTAL (B_ * A_)
#define NTILES (ROWS_TOTAL / TM)

// dynamic smem layout in bf16 elements (rows padded to 40 bf16 = 80 B)
#define FROW 40
#define FH_OFF(b) ((b) * 5120)
#define FL_OFF(b) ((b) * 5120 + 2560)
#define WH_OFF(b) (10240 + (b) * 20480)
#define WL_OFF(b) (10240 + (b) * 20480 + 10240)
#define DSM_ELEMS 51200   // 102400 bytes

__device__ int g_cnt[8];          // statically zero; reset by last CTA each call
__device__ int g_done;
__device__ int g_lists[6][ROWS_TOTAL];
__device__ __nv_bfloat16 g_wh[6 * 256 * KPAD];
__device__ __nv_bfloat16 g_wl[6 * 256 * KPAD];

__device__ __forceinline__ float sigf(float z) {
    return __fdividef(1.f, 1.f + __expf(-z));
}
__device__ __forceinline__ uint32_t smem_u32(const void* p) {
    uint32_t a;
    asm("{ .reg .u64 t; cvta.to.shared.u64 t, %1; cvt.u32.u64 %0, t; }" : "=r"(a) : "l"(p));
    return a;
}
__device__ __forceinline__ uint32_t pkbf(__nv_bfloat16 a, __nv_bfloat16 b) {
    return (uint32_t)__bfloat16_as_ushort(a) | ((uint32_t)__bfloat16_as_ushort(b) << 16);
}
#define LDM_X4(r0, r1, r2, r3, addr) \
    asm volatile("ldmatrix.sync.aligned.m8n8.x4.shared.b16 {%0,%1,%2,%3}, [%4];" \
        : "=r"(r0), "=r"(r1), "=r"(r2), "=r"(r3) : "r"(addr))
#define MMA_BF16(c, a0, a1, a2, a3, b0, b1) \
    asm volatile("mma.sync.aligned.m16n8k16.row.col.f32.bf16.bf16.f32 " \
        "{%0,%1,%2,%3}, {%4,%5,%6,%7}, {%8,%9}, {%0,%1,%2,%3};" \
        : "+f"((c)[0]), "+f"((c)[1]), "+f"((c)[2]), "+f"((c)[3]) \
        : "r"(a0), "r"(a1), "r"(a2), "r"(a3), "r"(b0), "r"(b1))

__global__ void classify_kernel(const int* __restrict__ edges) {
    int rid = blockIdx.x * blockDim.x + threadIdx.x;
    const int* e = edges + (size_t)rid * D_;
    int d = 0;
    #pragma unroll
    for (int j = 0; j < D_; j++) d += (e[j] >= 0);
    unsigned lt = (1u << (threadIdx.x & 31)) - 1u;
    #pragma unroll
    for (int dd = 0; dd < 6; dd++) {
        unsigned m = __ballot_sync(0xffffffffu, d == dd);
        if (d == dd) {
            int leader = __ffs(m) - 1;
            int base = 0;
            if ((int)(threadIdx.x & 31) == leader) base = atomicAdd(&g_cnt[dd], __popc(m));
            base = __shfl_sync(m, base, leader);
            g_lists[dd][base + __popc(m & lt)] = rid;
        }
    }
}

// transpose + bf16-split degW[6][262][256] -> g_wh/g_wl[6][256][288] (n-major)
__global__ void wsplit_kernel(const float* __restrict__ degW) {
    __shared__ float t[32][33];
    int d = blockIdx.z, k0 = blockIdx.x * 32, n0 = blockIdx.y * 32;
    int x = threadIdx.x, y = threadIdx.y;
    #pragma unroll
    for (int yy = 0; yy < 4; yy++) {
        int k = k0 + y + yy * 8;
        t[y + yy * 8][x] = (k < K_) ? degW[((size_t)d * K_ + k) * 256 + n0 + x] : 0.f;
    }
    __syncthreads();
    #pragma unroll
    for (int yy = 0; yy < 4; yy++) {
        int n = n0 + y + yy * 8, k = k0 + x;
        float v = t[x][y + yy * 8];
        __nv_bfloat16 hi = __float2bfloat16(v);
        __nv_bfloat16 lo = __float2bfloat16(v - __bfloat162float(hi));
        size_t o = ((size_t)d * 256 + n) * KPAD + k;
        g_wh[o] = hi;
        g_wl[o] = lo;
    }
}

// ---- build one 32-k chunk of feats, bf16 hi/lo, rows padded to 80B ----
__device__ __forceinline__ void build_chunk(__nv_bfloat16* __restrict__ dsm, int b, int c,
                                            const float* __restrict__ atoms,
                                            const float* __restrict__ bonds,
                                            const int* __restrict__ rid_s,
                                            const int* __restrict__ edg_s) {
    const int tid = threadIdx.x;
    __nv_bfloat16* fh = dsm + FH_OFF(b);
    __nv_bfloat16* fl = dsm + FL_OFF(b);
    #pragma unroll
    for (int it = 0; it < 2; it++) {
        int job = it * NTHR + tid;
        int r = job >> 3, c4 = job & 7;         // r 0..63, c4 0..7 (4 k each)
        float4 v;
        if (c < 8) {
            const float4* a4 = (const float4*)atoms;
            int rid = rid_s[r];
            int cg = c * 8 + c4;
            v = a4[(size_t)rid * 64 + cg];
            int bbase = rid & ~(A_ - 1);
            #pragma unroll
            for (int j = 0; j < D_; j++) {
                int e = edg_s[r * D_ + j];
                if (e >= 0) {
                    float4 n = a4[(size_t)(bbase + e) * 64 + cg];
                    v.x += n.x; v.y += n.y; v.z += n.z; v.w += n.w;
                }
            }
        } else {
            v = make_float4(0.f, 0.f, 0.f, 0.f);
            if (c4 < 2) {
                const float* bb = bonds + (size_t)rid_s[r] * (D_ * NB_);
                float s[4] = {0.f, 0.f, 0.f, 0.f};
                #pragma unroll
                for (int q = 0; q < 4; q++) {
                    int nb = c4 * 4 + q;
                    if (nb < NB_) {
                        #pragma unroll
                        for (int j = 0; j < D_; j++) s[q] += bb[j * NB_ + nb];
                    }
                }
                v = make_float4(s[0], s[1], s[2], s[3]);
            }
        }
        __nv_bfloat16 h[4], l[4];
        float vv[4] = { v.x, v.y, v.z, v.w };
        #pragma unroll
        for (int q = 0; q < 4; q++) {
            h[q] = __float2bfloat16(vv[q]);
            l[q] = __float2bfloat16(vv[q] - __bfloat162float(h[q]));
        }
        uint2 uh = make_uint2(pkbf(h[0], h[1]), pkbf(h[2], h[3]));
        uint2 ul = make_uint2(pkbf(l[0], l[1]), pkbf(l[2], l[3]));
        *(uint2*)(fh + r * FROW + c4 * 4) = uh;
        *(uint2*)(fl + r * FROW + c4 * 4) = ul;
    }
}

// ---- stage chunk weights (n-major, 64B per col) into padded smem ----
__device__ __forceinline__ void wload(__nv_bfloat16* __restrict__ dsm, int b, int c, int d) {
    const int col = threadIdx.x;
    const __nv_bfloat16* sh = g_wh + ((size_t)d * 256 + col) * KPAD + c * CHK;
    const __nv_bfloat16* sl = g_wl + ((size_t)d * 256 + col) * KPAD + c * CHK;
    __nv_bfloat16* wh = dsm + WH_OFF(b) + col * FROW;
    __nv_bfloat16* wl = dsm + WL_OFF(b) + col * FROW;
    #pragma unroll
    for (int i = 0; i < 4; i++) {
        *(uint4*)(wh + i * 8) = *(const uint4*)(sh + i * 8);
        *(uint4*)(wl + i * 8) = *(const uint4*)(sl + i * 8);
    }
}

__global__ void __launch_bounds__(NTHR, 2)
nfp_gemm(const float* __restrict__ atoms,
         const float* __restrict__ bonds,
         const int*   __restrict__ edges,
         const float* __restrict__ degW,
         const float* __restrict__ bias,
         float*       __restrict__ out)
{
    extern __shared__ __align__(16) __nv_bfloat16 dsm[];
    __shared__ int      rid_s[TM];
    __shared__ int      deg_s[TM];
    __shared__ int      edg_s[TM * D_];
    __shared__ float    bias_s[O_];
    __shared__ unsigned pres_s;

    const int tid = threadIdx.x;
    if (tid == 0) pres_s = 0u;
    __syncthreads();

    // ---- map tile slots -> bucketed rows ----
    if (tid < TM) {
        int s = blockIdx.x * TM + tid;
        int accc = 0, d = 0, idx = 0;
        #pragma unroll
        for (int dd = 0; dd < 6; dd++) {
            int ccnt = g_cnt[dd];
            if (s >= accc && s < accc + ccnt) { d = dd; idx = s - accc; }
            accc += ccnt;
        }
        int rid = g_lists[d][idx];
        rid_s[tid] = rid;
        deg_s[tid] = d;
        atomicOr(&pres_s, 1u << d);
        const int* e = edges + (size_t)rid * D_;
        #pragma unroll
        for (int j = 0; j < D_; j++) edg_s[tid * D_ + j] = e[j];
    }
    bias_s[tid] = bias[tid];
    __syncthreads();

    const int lane = tid & 31;
    const int wid  = tid >> 5;
    const int mstripe = wid & 3;            // 16-row stripe
    const int nhalf   = wid >> 2;           // 128-col half
    const int quad = lane >> 3, sub = lane & 7;
    const int g = lane >> 2, tql = lane & 3;
    const unsigned pres = pres_s;
    const uint32_t dbase = smem_u32(dsm);

    // per-lane ldmatrix address components (bytes)
    const uint32_t a_off = (uint32_t)(mstripe * 16 + ((quad & 1) << 3) + sub) * 80
                         + ((quad >> 1) << 4);
    const uint32_t b_off = (uint32_t)(nhalf * 128 + ((quad >> 1) << 3) + sub) * 80
                         + ((quad & 1) << 4);

    for (int d = 0; d < 6; d++) {
        if (!((pres >> d) & 1u)) continue;       // uniform branch

        float acc[16][4];
        #pragma unroll
        for (int q = 0; q < 16; q++)
            #pragma unroll
            for (int cc = 0; cc < 4; cc++) acc[q][cc] = 0.f;

        build_chunk(dsm, 0, 0, atoms, bonds, rid_s, edg_s);
        wload(dsm, 0, 0, d);
        __syncthreads();

        #pragma unroll 1
        for (int c = 0; c < NC; c++) {
            if (c + 1 < NC) {
                build_chunk(dsm, (c + 1) & 1, c + 1, atoms, bonds, rid_s, edg_s);
                wload(dsm, (c + 1) & 1, c + 1, d);
            }
            const int b = c & 1;
            const uint32_t fh_b = dbase + FH_OFF(b) * 2 + a_off;
            const uint32_t fl_b = dbase + FL_OFF(b) * 2 + a_off;
            const uint32_t wh_b = dbase + WH_OFF(b) * 2 + b_off;
            const uint32_t wl_b = dbase + WL_OFF(b) * 2 + b_off;

            #pragma unroll
            for (int s = 0; s < 2; s++) {        // two k16 steps per chunk
                uint32_t ah0, ah1, ah2, ah3, al0, al1, al2, al3;
                LDM_X4(ah0, ah1, ah2, ah3, fh_b + s * 32);
                LDM_X4(al0, al1, al2, al3, fl_b + s * 32);
                #pragma unroll
                for (int p = 0; p < 8; p++) {    // 8 N-tile pairs (16 cols each)
                    uint32_t bh0, bh1, bh2, bh3, bl0, bl1, bl2, bl3;
                    LDM_X4(bh0, bh1, bh2, bh3, wh_b + p * 1280 + s * 32);
                    LDM_X4(bl0, bl1, bl2, bl3, wl_b + p * 1280 + s * 32);
                    MMA_BF16(acc[2 * p + 0], ah0, ah1, ah2, ah3, bh0, bh1);
                    MMA_BF16(acc[2 * p + 0], ah0, ah1, ah2, ah3, bl0, bl1);
                    MMA_BF16(acc[2 * p + 0], al0, al1, al2, al3, bh0, bh1);
                    MMA_BF16(acc[2 * p + 1], ah0, ah1, ah2, ah3, bh2, bh3);
                    MMA_BF16(acc[2 * p + 1], ah0, ah1, ah2, ah3, bl2, bl3);
                    MMA_BF16(acc[2 * p + 1], al0, al1, al2, al3, bh2, bh3);
                }
            }
            __syncthreads();
        }

        // ---- epilogue: rows mstripe*16+g (+8), cols nhalf*128 + nt*8 + 2t ----
        const int r0 = mstripe * 16 + g;
        const int r1 = r0 + 8;
        const bool m0 = (deg_s[r0] == d);
        const bool m1 = (deg_s[r1] == d);
        float* o0 = out + (size_t)rid_s[r0] * O_;
        float* o1 = out + (size_t)rid_s[r1] * O_;
        #pragma unroll
        for (int nt = 0; nt < 16; nt++) {
            int col = nhalf * 128 + nt * 8 + 2 * tql;
            float b0 = bias_s[col], b1 = bias_s[col + 1];
            if (m0) {
                float2 v = make_float2(sigf(acc[nt][0] + b0), sigf(acc[nt][1] + b1));
                *(float2*)(o0 + col) = v;
            }
            if (m1) {
                float2 v = make_float2(sigf(acc[nt][2] + b0), sigf(acc[nt][3] + b1));
                *(float2*)(o1 + col) = v;
            }
        }
    }

    // ---- self-resetting state for the next call ----
    __syncthreads();
    if (tid == 0) {
        int v = atomicAdd(&g_done, 1);
        if (v == NTILES - 1) {
            #pragma unroll
            for (int i = 0; i < 8; i++) g_cnt[i] = 0;
            g_done = 0;
            __threadfence();
        }
    }
}

extern "C" void kernel_launch(void* const* d_in, const int* in_sizes, int n_in,
                              void* d_out, int out_size) {
    const float* atoms = (const float*)d_in[0];
    const float* bonds = (const float*)d_in[1];
    const int*   edges = (const int*)d_in[2];
    const float* degW  = (const float*)d_in[3];
    const float* bvec  = (const float*)d_in[4];
    float* out = (float*)d_out;

    const int dsm_bytes = DSM_ELEMS * 2;    // 102400 B
    cudaFuncSetAttribute(nfp_gemm, cudaFuncAttributeMaxDynamicSharedMemorySize, dsm_bytes);

    classify_kernel<<<ROWS_TOTAL / 256, 256>>>(edges);
    wsplit_kernel<<<dim3(KPAD / 32, 256 / 32, 6), dim3(32, 8)>>>(degW);
    nfp_gemm<<<NTILES, NTHR, dsm_bytes>>>(atoms, bonds, edges, degW, bvec, out);
}

// round 17
// speedup vs baseline: 1.0957x; 1.0957x over previous
#include <cuda_runtime.h>
#include <cuda_bf16.h>
#include <cstdint>

#define B_   64
#define A_   1024
#define D_   5
#define F_   256
#define NB_  6
#define O_   256
#define K_   262
#define KPAD 288
#define TM   64
#define NTHR 256
#define CHK  32
#define NC   9            // 9 uniform chunks of 32 k (k >= 262 zero-padded)
#define ROWS_TOTAL (B_ * A_)
#define NTILES (ROWS_TOTAL / TM)

// dynamic smem layout in bf16 elements (rows padded to 40 bf16 = 80 B)
#define FROW 40
#define FH_OFF(b) ((b) * 5120)
#define FL_OFF(b) ((b) * 5120 + 2560)
#define WH_OFF(b) (10240 + (b) * 20480)
#define WL_OFF(b) (10240 + (b) * 20480 + 10240)
#define DSM_ELEMS 51200   // 102400 bytes

__device__ int g_cnt[8];          // statically zero; reset by last CTA each call
__device__ int g_done;
__device__ int g_lists[6][ROWS_TOTAL];
__device__ __nv_bfloat16 g_wh[6 * 256 * KPAD];
__device__ __nv_bfloat16 g_wl[6 * 256 * KPAD];

__device__ __forceinline__ float sigf(float z) {
    return __fdividef(1.f, 1.f + __expf(-z));
}
__device__ __forceinline__ uint32_t smem_u32(const void* p) {
    uint32_t a;
    asm("{ .reg .u64 t; cvta.to.shared.u64 t, %1; cvt.u32.u64 %0, t; }" : "=r"(a) : "l"(p));
    return a;
}
__device__ __forceinline__ uint32_t pkbf(__nv_bfloat16 a, __nv_bfloat16 b) {
    return (uint32_t)__bfloat16_as_ushort(a) | ((uint32_t)__bfloat16_as_ushort(b) << 16);
}
__device__ __forceinline__ void cpasync16(uint32_t dst, const void* src) {
    asm volatile("cp.async.cg.shared.global [%0], [%1], 16;" :: "r"(dst), "l"(src));
}
#define CPASYNC_COMMIT() asm volatile("cp.async.commit_group;" ::: "memory")
#define CPASYNC_WAIT0()  asm volatile("cp.async.wait_group 0;" ::: "memory")
#define LDM_X4(r0, r1, r2, r3, addr) \
    asm volatile("ldmatrix.sync.aligned.m8n8.x4.shared.b16 {%0,%1,%2,%3}, [%4];" \
        : "=r"(r0), "=r"(r1), "=r"(r2), "=r"(r3) : "r"(addr))
#define MMA_BF16(c, a0, a1, a2, a3, b0, b1) \
    asm volatile("mma.sync.aligned.m16n8k16.row.col.f32.bf16.bf16.f32 " \
        "{%0,%1,%2,%3}, {%4,%5,%6,%7}, {%8,%9}, {%0,%1,%2,%3};" \
        : "+f"((c)[0]), "+f"((c)[1]), "+f"((c)[2]), "+f"((c)[3]) \
        : "r"(a0), "r"(a1), "r"(a2), "r"(a3), "r"(b0), "r"(b1))

__global__ void classify_kernel(const int* __restrict__ edges) {
    int rid = blockIdx.x * blockDim.x + threadIdx.x;
    const int* e = edges + (size_t)rid * D_;
    int d = 0;
    #pragma unroll
    for (int j = 0; j < D_; j++) d += (e[j] >= 0);
    unsigned lt = (1u << (threadIdx.x & 31)) - 1u;
    #pragma unroll
    for (int dd = 0; dd < 6; dd++) {
        unsigned m = __ballot_sync(0xffffffffu, d == dd);
        if (d == dd) {
            int leader = __ffs(m) - 1;
            int base = 0;
            if ((int)(threadIdx.x & 31) == leader) base = atomicAdd(&g_cnt[dd], __popc(m));
            base = __shfl_sync(m, base, leader);
            g_lists[dd][base + __popc(m & lt)] = rid;
        }
    }
}

// transpose + bf16-split degW[6][262][256] -> g_wh/g_wl[6][256][288] (n-major)
__global__ void wsplit_kernel(const float* __restrict__ degW) {
    __shared__ float t[32][33];
    int d = blockIdx.z, k0 = blockIdx.x * 32, n0 = blockIdx.y * 32;
    int x = threadIdx.x, y = threadIdx.y;
    #pragma unroll
    for (int yy = 0; yy < 4; yy++) {
        int k = k0 + y + yy * 8;
        t[y + yy * 8][x] = (k < K_) ? degW[((size_t)d * K_ + k) * 256 + n0 + x] : 0.f;
    }
    __syncthreads();
    #pragma unroll
    for (int yy = 0; yy < 4; yy++) {
        int n = n0 + y + yy * 8, k = k0 + x;
        float v = t[x][y + yy * 8];
        __nv_bfloat16 hi = __float2bfloat16(v);
        __nv_bfloat16 lo = __float2bfloat16(v - __bfloat162float(hi));
        size_t o = ((size_t)d * 256 + n) * KPAD + k;
        g_wh[o] = hi;
        g_wl[o] = lo;
    }
}

// ---- build one 32-k chunk of feats, bf16 hi/lo, rows padded to 80B ----
__device__ __forceinline__ void build_chunk(__nv_bfloat16* __restrict__ dsm, int b, int c,
                                            const float* __restrict__ atoms,
                                            const float* __restrict__ bonds,
                                            const int* __restrict__ rid_s,
                                            const int* __restrict__ edg_s) {
    const int tid = threadIdx.x;
    __nv_bfloat16* fh = dsm + FH_OFF(b);
    __nv_bfloat16* fl = dsm + FL_OFF(b);
    #pragma unroll
    for (int it = 0; it < 2; it++) {
        int job = it * NTHR + tid;
        int r = job >> 3, c4 = job & 7;         // r 0..63, c4 0..7 (4 k each)
        float4 v;
        if (c < 8) {
            const float4* a4 = (const float4*)atoms;
            int rid = rid_s[r];
            int cg = c * 8 + c4;
            v = a4[(size_t)rid * 64 + cg];
            int bbase = rid & ~(A_ - 1);
            #pragma unroll
            for (int j = 0; j < D_; j++) {
                int e = edg_s[r * D_ + j];
                if (e >= 0) {
                    float4 n = a4[(size_t)(bbase + e) * 64 + cg];
                    v.x += n.x; v.y += n.y; v.z += n.z; v.w += n.w;
                }
            }
        } else {
            v = make_float4(0.f, 0.f, 0.f, 0.f);
            if (c4 < 2) {
                const float* bb = bonds + (size_t)rid_s[r] * (D_ * NB_);
                float s[4] = {0.f, 0.f, 0.f, 0.f};
                #pragma unroll
                for (int q = 0; q < 4; q++) {
                    int nb = c4 * 4 + q;
                    if (nb < NB_) {
                        #pragma unroll
                        for (int j = 0; j < D_; j++) s[q] += bb[j * NB_ + nb];
                    }
                }
                v = make_float4(s[0], s[1], s[2], s[3]);
            }
        }
        __nv_bfloat16 h[4], l[4];
        float vv[4] = { v.x, v.y, v.z, v.w };
        #pragma unroll
        for (int q = 0; q < 4; q++) {
            h[q] = __float2bfloat16(vv[q]);
            l[q] = __float2bfloat16(vv[q] - __bfloat162float(h[q]));
        }
        uint2 uh = make_uint2(pkbf(h[0], h[1]), pkbf(h[2], h[3]));
        uint2 ul = make_uint2(pkbf(l[0], l[1]), pkbf(l[2], l[3]));
        *(uint2*)(fh + r * FROW + c4 * 4) = uh;
        *(uint2*)(fl + r * FROW + c4 * 4) = ul;
    }
}

// ---- async stage chunk weights (n-major, 64B hi + 64B lo per col) ----
__device__ __forceinline__ void wload_async(uint32_t dbase, int b, int c, int d) {
    const int col = threadIdx.x;
    const __nv_bfloat16* sh = g_wh + ((size_t)d * 256 + col) * KPAD + c * CHK;
    const __nv_bfloat16* sl = g_wl + ((size_t)d * 256 + col) * KPAD + c * CHK;
    uint32_t wh = dbase + (uint32_t)(WH_OFF(b) + col * FROW) * 2;
    uint32_t wl = dbase + (uint32_t)(WL_OFF(b) + col * FROW) * 2;
    #pragma unroll
    for (int i = 0; i < 4; i++) {
        cpasync16(wh + i * 16, sh + i * 8);
        cpasync16(wl + i * 16, sl + i * 8);
    }
    CPASYNC_COMMIT();
}

__global__ void __launch_bounds__(NTHR, 2)
nfp_gemm(const float* __restrict__ atoms,
         const float* __restrict__ bonds,
         const int*   __restrict__ edges,
         const float* __restrict__ degW,
         const float* __restrict__ bias,
         float*       __restrict__ out)
{
    extern __shared__ __align__(16) __nv_bfloat16 dsm[];
    __shared__ int      rid_s[TM];
    __shared__ int      deg_s[TM];
    __shared__ int      edg_s[TM * D_];
    __shared__ float    bias_s[O_];
    __shared__ unsigned pres_s;

    const int tid = threadIdx.x;
    if (tid == 0) pres_s = 0u;
    __syncthreads();

    // ---- map tile slots -> bucketed rows ----
    if (tid < TM) {
        int s = blockIdx.x * TM + tid;
        int accc = 0, d = 0, idx = 0;
        #pragma unroll
        for (int dd = 0; dd < 6; dd++) {
            int ccnt = g_cnt[dd];
            if (s >= accc && s < accc + ccnt) { d = dd; idx = s - accc; }
            accc += ccnt;
        }
        int rid = g_lists[d][idx];
        rid_s[tid] = rid;
        deg_s[tid] = d;
        atomicOr(&pres_s, 1u << d);
        const int* e = edges + (size_t)rid * D_;
        #pragma unroll
        for (int j = 0; j < D_; j++) edg_s[tid * D_ + j] = e[j];
    }
    bias_s[tid] = bias[tid];
    __syncthreads();

    const int lane = tid & 31;
    const int wid  = tid >> 5;
    const int mstripe = wid & 3;            // 16-row stripe
    const int nhalf   = wid >> 2;           // 128-col half
    const int quad = lane >> 3, sub = lane & 7;
    const int g = lane >> 2, tql = lane & 3;
    const unsigned pres = pres_s;
    const uint32_t dbase = smem_u32(dsm);

    // per-lane ldmatrix address components (bytes)
    const uint32_t a_off = (uint32_t)(mstripe * 16 + ((quad & 1) << 3) + sub) * 80
                         + ((quad >> 1) << 4);
    const uint32_t b_off = (uint32_t)(nhalf * 128 + ((quad >> 1) << 3) + sub) * 80
                         + ((quad & 1) << 4);

    for (int d = 0; d < 6; d++) {
        if (!((pres >> d) & 1u)) continue;       // uniform branch

        float acc[16][4];
        #pragma unroll
        for (int q = 0; q < 16; q++)
            #pragma unroll
            for (int cc = 0; cc < 4; cc++) acc[q][cc] = 0.f;

        // prologue: stage chunk 0 (weights async under the build latency)
        wload_async(dbase, 0, 0, d);
        build_chunk(dsm, 0, 0, atoms, bonds, rid_s, edg_s);
        CPASYNC_WAIT0();
        __syncthreads();

        #pragma unroll 1
        for (int c = 0; c < NC; c++) {
            // 1) issue next chunk's weight copies (zero-register, ~64 cyc)
            if (c + 1 < NC) wload_async(dbase, (c + 1) & 1, c + 1, d);

            // 2) MMA on current chunk — data ready, issues immediately
            const int b = c & 1;
            const uint32_t fh_b = dbase + FH_OFF(b) * 2 + a_off;
            const uint32_t fl_b = dbase + FL_OFF(b) * 2 + a_off;
            const uint32_t wh_b = dbase + WH_OFF(b) * 2 + b_off;
            const uint32_t wl_b = dbase + WL_OFF(b) * 2 + b_off;
            #pragma unroll
            for (int s = 0; s < 2; s++) {        // two k16 steps per chunk
                uint32_t ah0, ah1, ah2, ah3, al0, al1, al2, al3;
                LDM_X4(ah0, ah1, ah2, ah3, fh_b + s * 32);
                LDM_X4(al0, al1, al2, al3, fl_b + s * 32);
                #pragma unroll
                for (int p = 0; p < 8; p++) {    // 8 N-tile pairs (16 cols each)
                    uint32_t bh0, bh1, bh2, bh3, bl0, bl1, bl2, bl3;
                    LDM_X4(bh0, bh1, bh2, bh3, wh_b + p * 1280 + s * 32);
                    LDM_X4(bl0, bl1, bl2, bl3, wl_b + p * 1280 + s * 32);
                    MMA_BF16(acc[2 * p + 0], ah0, ah1, ah2, ah3, bh0, bh1);
                    MMA_BF16(acc[2 * p + 0], ah0, ah1, ah2, ah3, bl0, bl1);
                    MMA_BF16(acc[2 * p + 0], al0, al1, al2, al3, bh0, bh1);
                    MMA_BF16(acc[2 * p + 1], ah0, ah1, ah2, ah3, bh2, bh3);
                    MMA_BF16(acc[2 * p + 1], ah0, ah1, ah2, ah3, bl2, bl3);
                    MMA_BF16(acc[2 * p + 1], al0, al1, al2, al3, bh2, bh3);
                }
            }

            // 3) build next feats chunk — LDG stalls overlap other warps' MMAs
            if (c + 1 < NC) build_chunk(dsm, (c + 1) & 1, c + 1, atoms, bonds, rid_s, edg_s);
            CPASYNC_WAIT0();
            __syncthreads();
        }

        // ---- epilogue: rows mstripe*16+g (+8), cols nhalf*128 + nt*8 + 2t ----
        const int r0 = mstripe * 16 + g;
        const int r1 = r0 + 8;
        const bool m0 = (deg_s[r0] == d);
        const bool m1 = (deg_s[r1] == d);
        float* o0 = out + (size_t)rid_s[r0] * O_;
        float* o1 = out + (size_t)rid_s[r1] * O_;
        #pragma unroll
        for (int nt = 0; nt < 16; nt++) {
            int col = nhalf * 128 + nt * 8 + 2 * tql;
            float b0 = bias_s[col], b1 = bias_s[col + 1];
            if (m0) {
                float2 v = make_float2(sigf(acc[nt][0] + b0), sigf(acc[nt][1] + b1));
                *(float2*)(o0 + col) = v;
            }
            if (m1) {
                float2 v = make_float2(sigf(acc[nt][2] + b0), sigf(acc[nt][3] + b1));
                *(float2*)(o1 + col) = v;
            }
        }
    }

    // ---- self-resetting state for the next call ----
    __syncthreads();
    if (tid == 0) {
        int v = atomicAdd(&g_done, 1);
        if (v == NTILES - 1) {
            #pragma unroll
            for (int i = 0; i < 8; i++) g_cnt[i] = 0;
            g_done = 0;
            __threadfence();
        }
    }
}

extern "C" void kernel_launch(void* const* d_in, const int* in_sizes, int n_in,
                              void* d_out, int out_size) {
    const float* atoms = (const float*)d_in[0];
    const float* bonds = (const float*)d_in[1];
    const int*   edges = (const int*)d_in[2];
    const float* degW  = (const float*)d_in[3];
    const float* bvec  = (const float*)d_in[4];
    float* out = (float*)d_out;

    const int dsm_bytes = DSM_ELEMS * 2;    // 102400 B
    cudaFuncSetAttribute(nfp_gemm, cudaFuncAttributeMaxDynamicSharedMemorySize, dsm_bytes);

    classify_kernel<<<ROWS_TOTAL / 256, 256>>>(edges);
    wsplit_kernel<<<dim3(KPAD / 32, 256 / 32, 6), dim3(32, 8)>>>(degW);
    nfp_gemm<<<NTILES, NTHR, dsm_bytes>>>(atoms, bonds, edges, degW, bvec, out);
}